// round 8
// baseline (speedup 1.0000x reference)
#include <cuda_runtime.h>
#include <cuda_bf16.h>
#include <cstdint>

// Problem constants (fixed shapes for this problem)
#define C_IMG 512
#define C_PT  256
#define MAX_M (8 * 48 * 160)   // BS*H*W = 61440 pixels
#define MAX_N 131072           // >= point count (100000)

// Static device scratch
__device__ float g_G[(size_t)MAX_M * C_PT];   // GEMM output: 61440 x 256 (62.9 MB)
__device__ float g_Wt[C_IMG * C_PT];          // W^T, tf32-rounded: [512 k][256 n]
__device__ float4 g_wts[MAX_N];               // per-point bilinear weights
__device__ int4   g_offs[MAX_N];              // per-point G offsets (premultiplied by C_PT)

__device__ __forceinline__ float to_tf32(float x) {
    uint32_t u;
    asm("cvt.rna.tf32.f32 %0, %1;" : "=r"(u) : "f"(x));
    return __uint_as_float(u);
}

// mma.sync tf32 m16n8k8 (sm_80+; compiles for plain sm_103)
__device__ __forceinline__ void mma_tf32(float* d, const uint32_t* a, const uint32_t* b) {
    asm volatile(
        "mma.sync.aligned.m16n8k8.row.col.f32.tf32.tf32.f32 "
        "{%0,%1,%2,%3}, {%4,%5,%6,%7}, {%8,%9}, {%0,%1,%2,%3};"
        : "+f"(d[0]), "+f"(d[1]), "+f"(d[2]), "+f"(d[3])
        : "r"(a[0]), "r"(a[1]), "r"(a[2]), "r"(a[3]),
          "r"(b[0]), "r"(b[1]));
}

__device__ __forceinline__ void cp16(uint32_t smem_dst, const void* gsrc) {
    asm volatile("cp.async.cg.shared.global [%0], [%1], 16;"
                 :: "r"(smem_dst), "l"(gsrc) : "memory");
}

// ---------------------------------------------------------------------------
// Phase 0: transpose align_w (256x512) -> g_Wt [512][256], tf32-rounded
// ---------------------------------------------------------------------------
__global__ void transpose_w(const float* __restrict__ W) {
    __shared__ float tile[32][33];
    int kb = blockIdx.x * 32;
    int cb = blockIdx.y * 32;
    int tx = threadIdx.x, ty = threadIdx.y;
    #pragma unroll
    for (int i = ty; i < 32; i += 8)
        tile[i][tx] = W[(size_t)(cb + i) * C_IMG + kb + tx];
    __syncthreads();
    #pragma unroll
    for (int i = ty; i < 32; i += 8)
        g_Wt[(size_t)(kb + i) * C_PT + cb + tx] = to_tf32(tile[tx][i]);
}

// ---------------------------------------------------------------------------
// Phase 1: G[p, n] = sum_k img[b, k, hw] * W[n, k] via mma.sync tf32.
//   Block tile 128(M) x 128(N), BK=16, 8 warps (2x4), warp tile 64x32.
//   4-stage cp.async pipeline, prefetch distance 3.
//   Grid (N-tiles, M-tiles): adjacent CTAs share the A tile -> L2 reuse.
// ---------------------------------------------------------------------------
#define BM 128
#define BN 128
#define BK 16
#define APAD 136
#define NSTAGE 4
#define NCHUNK (C_IMG / BK)                // 32
#define STAGE_FLOATS (BK * APAD)           // 2176 floats = 8704 B
#define GEMM_SMEM (NSTAGE * 2 * STAGE_FLOATS * 4)   // 69632 B

__global__ __launch_bounds__(256, 2) void gemm_mma(const float* __restrict__ img, int HW) {
    extern __shared__ __align__(16) float dsm[];
    float* As = dsm;                               // [NSTAGE][BK][APAD]
    float* Bs = dsm + NSTAGE * STAGE_FLOATS;       // [NSTAGE][BK][APAD]

    const int tid  = threadIdx.x;
    const int wid  = tid >> 5;
    const int lane = tid & 31;
    const int g    = lane >> 2;     // group id 0..7
    const int tig  = lane & 3;      // thread-in-group 0..3
    const int wm   = (wid & 1) * 64;
    const int wn   = (wid >> 1) * 32;

    const int n0 = blockIdx.x * BN;   // N-tile runs fastest -> A tile L2 reuse
    const int m0 = blockIdx.y * BM;
    const int b  = m0 / HW;
    const int hw0 = m0 - b * HW;

    // global load mapping: thread covers 8 consecutive elements of one k-row
    const int lk = tid >> 4;          // 0..15
    const int lm = (tid & 15) * 8;    // 0..120

    const float* Abase = img + ((size_t)b * C_IMG + lk) * HW + hw0 + lm;
    const float* Bbase = g_Wt + (size_t)lk * C_PT + n0 + lm;

    const uint32_t sa = (uint32_t)__cvta_generic_to_shared(As) + (uint32_t)(lk * APAD + lm) * 4u;
    const uint32_t sb = (uint32_t)__cvta_generic_to_shared(Bs) + (uint32_t)(lk * APAD + lm) * 4u;

    // prologue: stages 0..2
    #pragma unroll
    for (int s = 0; s < NSTAGE - 1; s++) {
        const float* ap = Abase + (size_t)(s * BK) * HW;
        const float* bp = Bbase + (size_t)(s * BK) * C_PT;
        const uint32_t da = sa + s * (STAGE_FLOATS * 4);
        const uint32_t db = sb + s * (STAGE_FLOATS * 4);
        cp16(da,      ap);
        cp16(da + 16, ap + 4);
        cp16(db,      bp);
        cp16(db + 16, bp + 4);
        asm volatile("cp.async.commit_group;" ::: "memory");
    }

    float acc[4][4][4];
    #pragma unroll
    for (int i = 0; i < 4; i++)
        #pragma unroll
        for (int j = 0; j < 4; j++)
            #pragma unroll
            for (int r = 0; r < 4; r++) acc[i][j][r] = 0.f;

    for (int i = 0; i < NCHUNK; i++) {
        const int buf = i % NSTAGE;

        // groups committed so far = min(NCHUNK, i+3); need group i done.
        if (i <= NCHUNK - 3) {
            asm volatile("cp.async.wait_group 2;" ::: "memory");
        } else if (i == NCHUNK - 2) {
            asm volatile("cp.async.wait_group 1;" ::: "memory");
        } else {
            asm volatile("cp.async.wait_group 0;" ::: "memory");
        }
        __syncthreads();   // stage i visible; compute on stage i-(NSTAGE-1) done

        if (i + NSTAGE - 1 < NCHUNK) {
            const int s = (i + NSTAGE - 1) % NSTAGE;
            const float* ap = Abase + (size_t)((i + NSTAGE - 1) * BK) * HW;
            const float* bp = Bbase + (size_t)((i + NSTAGE - 1) * BK) * C_PT;
            const uint32_t da = sa + s * (STAGE_FLOATS * 4);
            const uint32_t db = sb + s * (STAGE_FLOATS * 4);
            cp16(da,      ap);
            cp16(da + 16, ap + 4);
            cp16(db,      bp);
            cp16(db + 16, bp + 4);
            asm volatile("cp.async.commit_group;" ::: "memory");
        }

        const float* as = As + buf * STAGE_FLOATS;
        const float* bs = Bs + buf * STAGE_FLOATS;
        #pragma unroll
        for (int ks = 0; ks < BK; ks += 8) {
            uint32_t af[4][4], bf[4][2];
            #pragma unroll
            for (int mf = 0; mf < 4; mf++) {
                const int m = wm + mf * 16 + g;
                af[mf][0] = __float_as_uint(as[(ks + tig)     * APAD + m]);
                af[mf][1] = __float_as_uint(as[(ks + tig)     * APAD + m + 8]);
                af[mf][2] = __float_as_uint(as[(ks + tig + 4) * APAD + m]);
                af[mf][3] = __float_as_uint(as[(ks + tig + 4) * APAD + m + 8]);
            }
            #pragma unroll
            for (int nf = 0; nf < 4; nf++) {
                const int n = wn + nf * 8 + g;
                bf[nf][0] = __float_as_uint(bs[(ks + tig)     * APAD + n]);
                bf[nf][1] = __float_as_uint(bs[(ks + tig + 4) * APAD + n]);
            }
            #pragma unroll
            for (int mf = 0; mf < 4; mf++)
                #pragma unroll
                for (int nf = 0; nf < 4; nf++)
                    mma_tf32(acc[mf][nf], af[mf], bf[nf]);
        }
    }

    // Epilogue: c0,c1 -> row g, cols 2tig..2tig+1 ; c2,c3 -> row g+8
    #pragma unroll
    for (int mf = 0; mf < 4; mf++) {
        const int r0 = m0 + wm + mf * 16 + g;
        #pragma unroll
        for (int nf = 0; nf < 4; nf++) {
            const int c = n0 + wn + nf * 8 + 2 * tig;
            *reinterpret_cast<float2*>(g_G + (size_t)r0 * C_PT + c) =
                make_float2(acc[mf][nf][0], acc[mf][nf][1]);
            *reinterpret_cast<float2*>(g_G + (size_t)(r0 + 8) * C_PT + c) =
                make_float2(acc[mf][nf][2], acc[mf][nf][3]);
        }
    }
}

// ---------------------------------------------------------------------------
// Phase 2a: per-point projection -> weights + premultiplied G offsets
// ---------------------------------------------------------------------------
__global__ void proj_kernel(
    const float* __restrict__ centers,
    const float* __restrict__ P2,
    const float* __restrict__ R0,
    const float* __restrict__ Tr,
    const int*   __restrict__ bidx,
    const int*   __restrict__ hp,
    const int*   __restrict__ wp,
    int N)
{
    const int n = blockIdx.x * 256 + threadIdx.x;
    if (n >= N) return;

    const int b = bidx[n];
    const float px = centers[n * 3 + 0];
    const float py = centers[n * 3 + 1];
    const float pz = centers[n * 3 + 2];

    const float* tr = Tr + (size_t)b * 16;
    const float c0 = tr[0]  * px + tr[1]  * py + tr[2]  * pz + tr[3];
    const float c1 = tr[4]  * px + tr[5]  * py + tr[6]  * pz + tr[7];
    const float c2 = tr[8]  * px + tr[9]  * py + tr[10] * pz + tr[11];
    const float c3 = tr[12] * px + tr[13] * py + tr[14] * pz + tr[15];

    const float* r = R0 + (size_t)b * 16;
    const float e0 = r[0]  * c0 + r[1]  * c1 + r[2]  * c2 + r[3]  * c3;
    const float e1 = r[4]  * c0 + r[5]  * c1 + r[6]  * c2 + r[7]  * c3;
    const float e2 = r[8]  * c0 + r[9]  * c1 + r[10] * c2 + r[11] * c3;
    const float e3 = r[12] * c0 + r[13] * c1 + r[14] * c2 + r[15] * c3;

    const float* pm = P2 + (size_t)b * 12;
    const float iu = pm[0] * e0 + pm[1] * e1 + pm[2]  * e2 + pm[3]  * e3;
    const float iv = pm[4] * e0 + pm[5] * e1 + pm[6]  * e2 + pm[7]  * e3;
    const float iz = pm[8] * e0 + pm[9] * e1 + pm[10] * e2 + pm[11] * e3;

    const float depth = fmaxf(iz, 1e-5f);
    const float u = iu / depth;
    const float v = iv / depth;

    const int Wf = wp[0];
    const int Hf = hp[0];
    const bool valid = (iz > 0.f) && (u >= 0.f) && (u < (float)Wf) &&
                       (v >= 0.f) && (v < (float)Hf);

    const float x0f = floorf(u), y0f = floorf(v);
    const float wx1 = u - x0f, wx0 = 1.f - wx1;
    const float wy1 = v - y0f, wy0 = 1.f - wy1;
    const float vw = valid ? 1.f : 0.f;

    const float x1f = x0f + 1.f, y1f = y0f + 1.f;
    const bool bx0 = (x0f >= 0.f) && (x0f <= (float)(Wf - 1));
    const bool bx1 = (x1f >= 0.f) && (x1f <= (float)(Wf - 1));
    const bool by0 = (y0f >= 0.f) && (y0f <= (float)(Hf - 1));
    const bool by1 = (y1f >= 0.f) && (y1f <= (float)(Hf - 1));

    const float w00 = wx0 * wy0 * vw * (float)(bx0 && by0);
    const float w10 = wx1 * wy0 * vw * (float)(bx1 && by0);
    const float w01 = wx0 * wy1 * vw * (float)(bx0 && by1);
    const float w11 = wx1 * wy1 * vw * (float)(bx1 && by1);

    const int x0c = min(max((int)x0f, 0), Wf - 1);
    const int x1c = min(max((int)x0f + 1, 0), Wf - 1);
    const int y0c = min(max((int)y0f, 0), Hf - 1);
    const int y1c = min(max((int)y0f + 1, 0), Hf - 1);

    const int base_b = b * Hf * Wf;
    g_wts[n]  = make_float4(w00, w10, w01, w11);
    g_offs[n] = make_int4((base_b + y0c * Wf + x0c) * C_PT,
                          (base_b + y0c * Wf + x1c) * C_PT,
                          (base_b + y1c * Wf + x0c) * C_PT,
                          (base_b + y1c * Wf + x1c) * C_PT);
}

// ---------------------------------------------------------------------------
// Phase 2b: streaming blend: out = pf + bias + sum_i w_i * G[off_i]
// 64 threads per point (4 channels each), 4 points per block.
// Unconditional corner loads (offsets always clamped-valid) -> 6-deep MLP.
// ---------------------------------------------------------------------------
__global__ void blend_kernel(
    const float* __restrict__ pf,
    const float* __restrict__ ab,
    float*       __restrict__ out,
    int N)
{
    const int tid  = threadIdx.x;
    const int grp  = tid >> 6;
    const int lane = tid & 63;
    const int n = blockIdx.x * 4 + grp;
    if (n >= N) return;

    const float4 w = g_wts[n];
    const int4   o = g_offs[n];

    const int co = lane * 4;
    const float4 p  = *reinterpret_cast<const float4*>(pf + (size_t)n * C_PT + co);
    const float4 bb = *reinterpret_cast<const float4*>(ab + co);
    const float4 g0 = *reinterpret_cast<const float4*>(g_G + o.x + co);
    const float4 g1 = *reinterpret_cast<const float4*>(g_G + o.y + co);
    const float4 g2 = *reinterpret_cast<const float4*>(g_G + o.z + co);
    const float4 g3 = *reinterpret_cast<const float4*>(g_G + o.w + co);

    float4 acc;
    acc.x = p.x + bb.x; acc.y = p.y + bb.y; acc.z = p.z + bb.z; acc.w = p.w + bb.w;

    acc.x = fmaf(w.x, g0.x, acc.x); acc.y = fmaf(w.x, g0.y, acc.y);
    acc.z = fmaf(w.x, g0.z, acc.z); acc.w = fmaf(w.x, g0.w, acc.w);

    acc.x = fmaf(w.y, g1.x, acc.x); acc.y = fmaf(w.y, g1.y, acc.y);
    acc.z = fmaf(w.y, g1.z, acc.z); acc.w = fmaf(w.y, g1.w, acc.w);

    acc.x = fmaf(w.z, g2.x, acc.x); acc.y = fmaf(w.z, g2.y, acc.y);
    acc.z = fmaf(w.z, g2.z, acc.z); acc.w = fmaf(w.z, g2.w, acc.w);

    acc.x = fmaf(w.w, g3.x, acc.x); acc.y = fmaf(w.w, g3.y, acc.y);
    acc.z = fmaf(w.w, g3.z, acc.z); acc.w = fmaf(w.w, g3.w, acc.w);

    *reinterpret_cast<float4*>(out + (size_t)n * C_PT + co) = acc;
}

// ---------------------------------------------------------------------------
// Launch
// Input order (metadata): point_feat, pillar_centers, img_feat, P2, R0, Tr,
//                         align_w, align_b, batch_idx, img_h, img_w
// ---------------------------------------------------------------------------
extern "C" void kernel_launch(void* const* d_in, const int* in_sizes, int n_in,
                              void* d_out, int out_size) {
    const float* point_feat = (const float*)d_in[0];
    const float* centers    = (const float*)d_in[1];
    const float* img        = (const float*)d_in[2];
    const float* P2         = (const float*)d_in[3];
    const float* R0         = (const float*)d_in[4];
    const float* Tr         = (const float*)d_in[5];
    const float* align_w    = (const float*)d_in[6];
    const float* align_b    = (const float*)d_in[7];
    const int*   bidx       = (const int*)d_in[8];
    const int*   img_h      = (const int*)d_in[9];
    const int*   img_w      = (const int*)d_in[10];
    float* out = (float*)d_out;

    const int N  = in_sizes[8];
    const int BS = in_sizes[3] / 12;
    const int HW = in_sizes[2] / (BS * C_IMG);
    const int M  = BS * HW;

    cudaFuncSetAttribute(gemm_mma, cudaFuncAttributeMaxDynamicSharedMemorySize, GEMM_SMEM);

    // Phase 0: W^T (tf32-rounded)
    transpose_w<<<dim3(C_IMG / 32, C_PT / 32), dim3(32, 8)>>>(align_w);

    // Phase 2a: cheap projection (independent of GEMM)
    proj_kernel<<<(N + 255) / 256, 256>>>(centers, P2, R0, Tr, bidx, img_h, img_w, N);

    // Phase 1: G = img @ W^T via mma.sync tf32 (4-stage cp.async, N-fastest grid)
    gemm_mma<<<dim3(C_PT / BN, M / BM), 256, GEMM_SMEM>>>(img, HW);

    // Phase 2b: streaming blend
    blend_kernel<<<(N + 3) / 4, 256>>>(point_feat, align_b, out, N);
}

// round 9
// speedup vs baseline: 1.2269x; 1.2269x over previous
#include <cuda_runtime.h>
#include <cuda_fp16.h>
#include <cstdint>

// Problem constants (fixed shapes for this problem)
#define C_IMG 512
#define C_PT  256
#define MAX_M (8 * 48 * 160)   // BS*H*W = 61440 pixels
#define MAX_N 131072           // >= point count (100000)

// Static device scratch
__device__ float  g_G[(size_t)MAX_M * C_PT];     // GEMM output (62.9 MB)
__device__ __half g_Ah[(size_t)MAX_M * C_IMG];   // img in fp16, same [b][c][hw] layout (62.9 MB)
__device__ __half g_Bh[(size_t)C_PT * C_IMG];    // align_w in fp16, [n][k] (256 KB)
__device__ float4 g_wts[MAX_N];                  // per-point bilinear weights
__device__ int4   g_offs[MAX_N];                 // per-point G offsets (premultiplied by C_PT)

// fp16 mma m16n8k16, fp32 accumulate (sm_80+; compiles for plain sm_103)
__device__ __forceinline__ void mma_f16(float* d, const uint32_t* a, const uint32_t* b) {
    asm volatile(
        "mma.sync.aligned.m16n8k16.row.col.f32.f16.f16.f32 "
        "{%0,%1,%2,%3}, {%4,%5,%6,%7}, {%8,%9}, {%0,%1,%2,%3};"
        : "+f"(d[0]), "+f"(d[1]), "+f"(d[2]), "+f"(d[3])
        : "r"(a[0]), "r"(a[1]), "r"(a[2]), "r"(a[3]),
          "r"(b[0]), "r"(b[1]));
}

__device__ __forceinline__ void ldsm_x4_trans(uint32_t* r, uint32_t addr) {
    asm volatile("ldmatrix.sync.aligned.m8n8.x4.trans.shared.b16 {%0,%1,%2,%3}, [%4];"
                 : "=r"(r[0]), "=r"(r[1]), "=r"(r[2]), "=r"(r[3]) : "r"(addr));
}
__device__ __forceinline__ void ldsm_x2(uint32_t* r, uint32_t addr) {
    asm volatile("ldmatrix.sync.aligned.m8n8.x2.shared.b16 {%0,%1}, [%2];"
                 : "=r"(r[0]), "=r"(r[1]) : "r"(addr));
}

__device__ __forceinline__ void cp16(uint32_t smem_dst, const void* gsrc) {
    asm volatile("cp.async.cg.shared.global [%0], [%1], 16;"
                 :: "r"(smem_dst), "l"(gsrc) : "memory");
}

// ---------------------------------------------------------------------------
// Phase 0a: img fp32 -> fp16 (same layout, fully coalesced)
// ---------------------------------------------------------------------------
__global__ void convert_img(const float* __restrict__ src, int total) {
    const int i = (blockIdx.x * 256 + threadIdx.x) * 8;
    if (i >= total) return;
    const float4 v0 = *reinterpret_cast<const float4*>(src + i);
    const float4 v1 = *reinterpret_cast<const float4*>(src + i + 4);
    __half2 h[4];
    h[0] = __floats2half2_rn(v0.x, v0.y);
    h[1] = __floats2half2_rn(v0.z, v0.w);
    h[2] = __floats2half2_rn(v1.x, v1.y);
    h[3] = __floats2half2_rn(v1.z, v1.w);
    *reinterpret_cast<uint4*>(g_Ah + i) = *reinterpret_cast<uint4*>(h);
}

// Phase 0b: align_w fp32 -> fp16 (already [n][k]; no transpose needed for B)
__global__ void convert_w(const float* __restrict__ W) {
    const int i = (blockIdx.x * 256 + threadIdx.x) * 4;
    const float4 v = *reinterpret_cast<const float4*>(W + i);
    __half2 h[2];
    h[0] = __floats2half2_rn(v.x, v.y);
    h[1] = __floats2half2_rn(v.z, v.w);
    *reinterpret_cast<uint2*>(g_Bh + i) = *reinterpret_cast<uint2*>(h);
}

// ---------------------------------------------------------------------------
// Phase 1: G[m, n] = sum_k A[m][k] * W[n][k], fp16 mma m16n8k16.
//   Block tile 128(M) x 128(N), BK=16, 8 warps (2x4), warp tile 64x32.
//   As: [k][m] fp16 rows of 272 B (ldmatrix.x4.trans, conflict-free).
//   Bs: [n][k] fp16 rows of 48 B  (ldmatrix.x2,       conflict-free).
//   3-stage cp.async pipeline (R7 schedule, proven).
// ---------------------------------------------------------------------------
#define BM 128
#define BN 128
#define BK 16
#define APAD_A 136   // fp16 units per A row (128 + 8 pad) = 272 B
#define BPAD_B 24    // fp16 units per B row (16 + 8 pad)  = 48 B
#define NSTAGE 3
#define NCHUNK (C_IMG / BK)   // 32
#define A_STAGE (BK * APAD_A) // fp16 units
#define B_STAGE (BN * BPAD_B) // fp16 units

__global__ __launch_bounds__(256, 2) void gemm_mma(int HW) {
    __shared__ __align__(16) __half As[NSTAGE][BK][APAD_A];
    __shared__ __align__(16) __half Bs[NSTAGE][BN][BPAD_B];

    const int tid  = threadIdx.x;
    const int wid  = tid >> 5;
    const int lane = tid & 31;
    const int g    = lane >> 2;
    const int tig  = lane & 3;
    const int wm   = (wid & 1) * 64;
    const int wn   = (wid >> 1) * 32;

    const int m0 = blockIdx.x * BM;
    const int n0 = blockIdx.y * BN;
    const int b  = m0 / HW;
    const int hw0 = m0 - b * HW;

    // global->smem mapping
    const int ark = tid >> 4;          // A: k row 0..15
    const int arm = (tid & 15) * 8;    // A: 8 fp16 (16B) along m
    const int brn = tid >> 1;          // B: n row 0..127
    const int brk = (tid & 1) * 8;     // B: 8 fp16 (16B) along k

    const __half* Abase = g_Ah + ((size_t)b * C_IMG + ark) * HW + hw0 + arm;
    const __half* Bbase = g_Bh + (size_t)(n0 + brn) * C_IMG + brk;

    const uint32_t sa = (uint32_t)__cvta_generic_to_shared(&As[0][ark][arm]);
    const uint32_t sb = (uint32_t)__cvta_generic_to_shared(&Bs[0][brn][brk]);

    // prologue: stages 0 and 1
    #pragma unroll
    for (int s = 0; s < 2; s++) {
        cp16(sa + s * (A_STAGE * 2), Abase + (size_t)(s * BK) * HW);
        cp16(sb + s * (B_STAGE * 2), Bbase + s * BK);
        asm volatile("cp.async.commit_group;" ::: "memory");
    }

    // lane-constant fragment smem offsets (bytes)
    // A (.x4.trans): k row = ((lane>>4)<<3)+(lane&7), m col = +8 if bit3
    const uint32_t a_frag_off =
        ((uint32_t)((((lane >> 4) << 3) + (lane & 7)) * APAD_A +
                    wm + ((lane >> 3) & 1) * 8)) * 2u;
    // B (.x2): n row = wn + (lane&7), k col = +8 if bit3 (lanes 0..15 used)
    const uint32_t b_frag_off =
        ((uint32_t)((wn + (lane & 7)) * BPAD_B + ((lane >> 3) & 1) * 8)) * 2u;

    const uint32_t as0 = (uint32_t)__cvta_generic_to_shared(&As[0][0][0]);
    const uint32_t bs0 = (uint32_t)__cvta_generic_to_shared(&Bs[0][0][0]);

    float acc[4][4][4];
    #pragma unroll
    for (int i = 0; i < 4; i++)
        #pragma unroll
        for (int j = 0; j < 4; j++)
            #pragma unroll
            for (int r = 0; r < 4; r++) acc[i][j][r] = 0.f;

    for (int i = 0; i < NCHUNK; i++) {
        const int buf = i % NSTAGE;

        if (i < NCHUNK - 1) {
            asm volatile("cp.async.wait_group 1;" ::: "memory");
        } else {
            asm volatile("cp.async.wait_group 0;" ::: "memory");
        }
        __syncthreads();

        if (i + 2 < NCHUNK) {
            const int s = (i + 2) % NSTAGE;
            cp16(sa + s * (A_STAGE * 2), Abase + (size_t)((i + 2) * BK) * HW);
            cp16(sb + s * (B_STAGE * 2), Bbase + (i + 2) * BK);
            asm volatile("cp.async.commit_group;" ::: "memory");
        }

        const uint32_t as_b = as0 + buf * (A_STAGE * 2) + a_frag_off;
        const uint32_t bs_b = bs0 + buf * (B_STAGE * 2) + b_frag_off;

        uint32_t af[4][4], bf[4][2];
        #pragma unroll
        for (int mf = 0; mf < 4; mf++)
            ldsm_x4_trans(af[mf], as_b + (uint32_t)(mf * 16 * 2));
        #pragma unroll
        for (int nf = 0; nf < 4; nf++)
            ldsm_x2(bf[nf], bs_b + (uint32_t)(nf * 8 * BPAD_B * 2));

        #pragma unroll
        for (int mf = 0; mf < 4; mf++)
            #pragma unroll
            for (int nf = 0; nf < 4; nf++)
                mma_f16(acc[mf][nf], af[mf], bf[nf]);
    }

    // Epilogue: c0,c1 -> row g, cols 2tig..2tig+1 ; c2,c3 -> row g+8
    #pragma unroll
    for (int mf = 0; mf < 4; mf++) {
        const int r0 = m0 + wm + mf * 16 + g;
        #pragma unroll
        for (int nf = 0; nf < 4; nf++) {
            const int c = n0 + wn + nf * 8 + 2 * tig;
            *reinterpret_cast<float2*>(g_G + (size_t)r0 * C_PT + c) =
                make_float2(acc[mf][nf][0], acc[mf][nf][1]);
            *reinterpret_cast<float2*>(g_G + (size_t)(r0 + 8) * C_PT + c) =
                make_float2(acc[mf][nf][2], acc[mf][nf][3]);
        }
    }
}

// ---------------------------------------------------------------------------
// Phase 2a: per-point projection -> weights + premultiplied G offsets
// ---------------------------------------------------------------------------
__global__ void proj_kernel(
    const float* __restrict__ centers,
    const float* __restrict__ P2,
    const float* __restrict__ R0,
    const float* __restrict__ Tr,
    const int*   __restrict__ bidx,
    const int*   __restrict__ hp,
    const int*   __restrict__ wp,
    int N)
{
    const int n = blockIdx.x * 256 + threadIdx.x;
    if (n >= N) return;

    const int b = bidx[n];
    const float px = centers[n * 3 + 0];
    const float py = centers[n * 3 + 1];
    const float pz = centers[n * 3 + 2];

    const float* tr = Tr + (size_t)b * 16;
    const float c0 = tr[0]  * px + tr[1]  * py + tr[2]  * pz + tr[3];
    const float c1 = tr[4]  * px + tr[5]  * py + tr[6]  * pz + tr[7];
    const float c2 = tr[8]  * px + tr[9]  * py + tr[10] * pz + tr[11];
    const float c3 = tr[12] * px + tr[13] * py + tr[14] * pz + tr[15];

    const float* r = R0 + (size_t)b * 16;
    const float e0 = r[0]  * c0 + r[1]  * c1 + r[2]  * c2 + r[3]  * c3;
    const float e1 = r[4]  * c0 + r[5]  * c1 + r[6]  * c2 + r[7]  * c3;
    const float e2 = r[8]  * c0 + r[9]  * c1 + r[10] * c2 + r[11] * c3;
    const float e3 = r[12] * c0 + r[13] * c1 + r[14] * c2 + r[15] * c3;

    const float* pm = P2 + (size_t)b * 12;
    const float iu = pm[0] * e0 + pm[1] * e1 + pm[2]  * e2 + pm[3]  * e3;
    const float iv = pm[4] * e0 + pm[5] * e1 + pm[6]  * e2 + pm[7]  * e3;
    const float iz = pm[8] * e0 + pm[9] * e1 + pm[10] * e2 + pm[11] * e3;

    const float depth = fmaxf(iz, 1e-5f);
    const float u = iu / depth;
    const float v = iv / depth;

    const int Wf = wp[0];
    const int Hf = hp[0];
    const bool valid = (iz > 0.f) && (u >= 0.f) && (u < (float)Wf) &&
                       (v >= 0.f) && (v < (float)Hf);

    const float x0f = floorf(u), y0f = floorf(v);
    const float wx1 = u - x0f, wx0 = 1.f - wx1;
    const float wy1 = v - y0f, wy0 = 1.f - wy1;
    const float vw = valid ? 1.f : 0.f;

    const float x1f = x0f + 1.f, y1f = y0f + 1.f;
    const bool bx0 = (x0f >= 0.f) && (x0f <= (float)(Wf - 1));
    const bool bx1 = (x1f >= 0.f) && (x1f <= (float)(Wf - 1));
    const bool by0 = (y0f >= 0.f) && (y0f <= (float)(Hf - 1));
    const bool by1 = (y1f >= 0.f) && (y1f <= (float)(Hf - 1));

    const float w00 = wx0 * wy0 * vw * (float)(bx0 && by0);
    const float w10 = wx1 * wy0 * vw * (float)(bx1 && by0);
    const float w01 = wx0 * wy1 * vw * (float)(bx0 && by1);
    const float w11 = wx1 * wy1 * vw * (float)(bx1 && by1);

    const int x0c = min(max((int)x0f, 0), Wf - 1);
    const int x1c = min(max((int)x0f + 1, 0), Wf - 1);
    const int y0c = min(max((int)y0f, 0), Hf - 1);
    const int y1c = min(max((int)y0f + 1, 0), Hf - 1);

    const int base_b = b * Hf * Wf;
    g_wts[n]  = make_float4(w00, w10, w01, w11);
    g_offs[n] = make_int4((base_b + y0c * Wf + x0c) * C_PT,
                          (base_b + y0c * Wf + x1c) * C_PT,
                          (base_b + y1c * Wf + x0c) * C_PT,
                          (base_b + y1c * Wf + x1c) * C_PT);
}

// ---------------------------------------------------------------------------
// Phase 2b: streaming blend: out = pf + bias + sum_i w_i * G[off_i]
// 64 threads per point (4 channels each), 4 points per block.
// Conditional corner loads (R7-proven: skips traffic for zero weights).
// ---------------------------------------------------------------------------
__global__ void blend_kernel(
    const float* __restrict__ pf,
    const float* __restrict__ ab,
    float*       __restrict__ out,
    int N)
{
    const int tid  = threadIdx.x;
    const int grp  = tid >> 6;
    const int lane = tid & 63;
    const int n = blockIdx.x * 4 + grp;
    if (n >= N) return;

    const float4 w = g_wts[n];
    const int4   o = g_offs[n];

    const int co = lane * 4;
    float4 acc = *reinterpret_cast<const float4*>(pf + (size_t)n * C_PT + co);
    const float4 bb = *reinterpret_cast<const float4*>(ab + co);
    acc.x += bb.x; acc.y += bb.y; acc.z += bb.z; acc.w += bb.w;

    if (w.x != 0.f) {
        const float4 gv = *reinterpret_cast<const float4*>(g_G + o.x + co);
        acc.x = fmaf(w.x, gv.x, acc.x); acc.y = fmaf(w.x, gv.y, acc.y);
        acc.z = fmaf(w.x, gv.z, acc.z); acc.w = fmaf(w.x, gv.w, acc.w);
    }
    if (w.y != 0.f) {
        const float4 gv = *reinterpret_cast<const float4*>(g_G + o.y + co);
        acc.x = fmaf(w.y, gv.x, acc.x); acc.y = fmaf(w.y, gv.y, acc.y);
        acc.z = fmaf(w.y, gv.z, acc.z); acc.w = fmaf(w.y, gv.w, acc.w);
    }
    if (w.z != 0.f) {
        const float4 gv = *reinterpret_cast<const float4*>(g_G + o.z + co);
        acc.x = fmaf(w.z, gv.x, acc.x); acc.y = fmaf(w.z, gv.y, acc.y);
        acc.z = fmaf(w.z, gv.z, acc.z); acc.w = fmaf(w.z, gv.w, acc.w);
    }
    if (w.w != 0.f) {
        const float4 gv = *reinterpret_cast<const float4*>(g_G + o.w + co);
        acc.x = fmaf(w.w, gv.x, acc.x); acc.y = fmaf(w.w, gv.y, acc.y);
        acc.z = fmaf(w.w, gv.z, acc.z); acc.w = fmaf(w.w, gv.w, acc.w);
    }

    *reinterpret_cast<float4*>(out + (size_t)n * C_PT + co) = acc;
}

// ---------------------------------------------------------------------------
// Launch
// Input order (metadata): point_feat, pillar_centers, img_feat, P2, R0, Tr,
//                         align_w, align_b, batch_idx, img_h, img_w
// ---------------------------------------------------------------------------
extern "C" void kernel_launch(void* const* d_in, const int* in_sizes, int n_in,
                              void* d_out, int out_size) {
    const float* point_feat = (const float*)d_in[0];
    const float* centers    = (const float*)d_in[1];
    const float* img        = (const float*)d_in[2];
    const float* P2         = (const float*)d_in[3];
    const float* R0         = (const float*)d_in[4];
    const float* Tr         = (const float*)d_in[5];
    const float* align_w    = (const float*)d_in[6];
    const float* align_b    = (const float*)d_in[7];
    const int*   bidx       = (const int*)d_in[8];
    const int*   img_h      = (const int*)d_in[9];
    const int*   img_w      = (const int*)d_in[10];
    float* out = (float*)d_out;

    const int N  = in_sizes[8];
    const int BS = in_sizes[3] / 12;
    const int total_img = in_sizes[2];
    const int HW = total_img / (BS * C_IMG);
    const int M  = BS * HW;

    // Phase 0: fp16 conversions (coalesced; no transposes needed)
    convert_w<<<(C_PT * C_IMG) / (256 * 4), 256>>>(align_w);
    convert_img<<<(total_img / 8 + 255) / 256, 256>>>(img, total_img);

    // Phase 2a: cheap projection (independent of GEMM)
    proj_kernel<<<(N + 255) / 256, 256>>>(centers, P2, R0, Tr, bidx, img_h, img_w, N);

    // Phase 1: G = img @ W^T via fp16 mma m16n8k16 (3-stage cp.async)
    gemm_mma<<<dim3(M / BM, C_PT / BN), 256>>>(HW);

    // Phase 2b: streaming blend
    blend_kernel<<<(N + 3) / 4, 256>>>(point_feat, align_b, out, N);
}

// round 11
// speedup vs baseline: 1.2791x; 1.0425x over previous
#include <cuda_runtime.h>
#include <cuda_fp16.h>
#include <cstdint>

// Problem constants (fixed shapes for this problem)
#define C_IMG 512
#define C_PT  256
#define MAX_M (8 * 48 * 160)   // BS*H*W = 61440 pixels
#define MAX_N 131072           // >= point count (100000)

// Static device scratch
__device__ float  g_G[(size_t)MAX_M * C_PT];     // GEMM output (62.9 MB)
__device__ __half g_Ah[(size_t)MAX_M * C_IMG];   // img in fp16, same [b][c][hw] layout (62.9 MB)
__device__ __half g_Bh[(size_t)C_PT * C_IMG];    // align_w in fp16, [n][k] (256 KB)
__device__ float4 g_wts[MAX_N];                  // per-point bilinear weights
__device__ int4   g_offs[MAX_N];                 // per-point G offsets (premultiplied by C_PT)

// fp16 mma m16n8k16, fp32 accumulate (sm_80+; compiles for plain sm_103)
__device__ __forceinline__ void mma_f16(float* d, const uint32_t* a, const uint32_t* b) {
    asm volatile(
        "mma.sync.aligned.m16n8k16.row.col.f32.f16.f16.f32 "
        "{%0,%1,%2,%3}, {%4,%5,%6,%7}, {%8,%9}, {%0,%1,%2,%3};"
        : "+f"(d[0]), "+f"(d[1]), "+f"(d[2]), "+f"(d[3])
        : "r"(a[0]), "r"(a[1]), "r"(a[2]), "r"(a[3]),
          "r"(b[0]), "r"(b[1]));
}

__device__ __forceinline__ void ldsm_x4_trans(uint32_t* r, uint32_t addr) {
    asm volatile("ldmatrix.sync.aligned.m8n8.x4.trans.shared.b16 {%0,%1,%2,%3}, [%4];"
                 : "=r"(r[0]), "=r"(r[1]), "=r"(r[2]), "=r"(r[3]) : "r"(addr));
}
__device__ __forceinline__ void ldsm_x2(uint32_t* r, uint32_t addr) {
    asm volatile("ldmatrix.sync.aligned.m8n8.x2.shared.b16 {%0,%1}, [%2];"
                 : "=r"(r[0]), "=r"(r[1]) : "r"(addr));
}

__device__ __forceinline__ void cp16(uint32_t smem_dst, const void* gsrc) {
    asm volatile("cp.async.cg.shared.global [%0], [%1], 16;"
                 :: "r"(smem_dst), "l"(gsrc) : "memory");
}

// ---------------------------------------------------------------------------
// Phase 0a: img fp32 -> fp16 (same layout, fully coalesced)
// ---------------------------------------------------------------------------
__global__ void convert_img(const float* __restrict__ src, int total) {
    const int i = (blockIdx.x * 256 + threadIdx.x) * 8;
    if (i >= total) return;
    const float4 v0 = *reinterpret_cast<const float4*>(src + i);
    const float4 v1 = *reinterpret_cast<const float4*>(src + i + 4);
    __half2 h[4];
    h[0] = __floats2half2_rn(v0.x, v0.y);
    h[1] = __floats2half2_rn(v0.z, v0.w);
    h[2] = __floats2half2_rn(v1.x, v1.y);
    h[3] = __floats2half2_rn(v1.z, v1.w);
    *reinterpret_cast<uint4*>(g_Ah + i) = *reinterpret_cast<uint4*>(h);
}

// Phase 0b: align_w fp32 -> fp16 (already [n][k]; no transpose needed for B)
__global__ void convert_w(const float* __restrict__ W) {
    const int i = (blockIdx.x * 256 + threadIdx.x) * 4;
    const float4 v = *reinterpret_cast<const float4*>(W + i);
    __half2 h[2];
    h[0] = __floats2half2_rn(v.x, v.y);
    h[1] = __floats2half2_rn(v.z, v.w);
    *reinterpret_cast<uint2*>(g_Bh + i) = *reinterpret_cast<uint2*>(h);
}

// ---------------------------------------------------------------------------
// Phase 1: G[m, n] = sum_k A[m][k] * W[n][k], fp16 mma m16n8k16.
//   Block tile 128(M) x 128(N), BK=32 per stage (2 k-steps), 8 warps (2x4),
//   warp tile 64x32. 3-stage cp.async, prefetch distance 2.
//   Per barrier: 16 LDSM + 32 HMMA per warp (halved barrier count vs BK=16).
// ---------------------------------------------------------------------------
#define BM 128
#define BN 128
#define BK 32
#define APAD_A 136   // fp16 units per A k-row (128 + 8 pad)  = 272 B
#define BPAD_B 40    // fp16 units per B n-row (32 + 8 pad)   = 80 B
#define NSTAGE 3
#define NCHUNK (C_IMG / BK)       // 16
#define A_STAGE (BK * APAD_A)     // 4352 fp16
#define B_STAGE (BN * BPAD_B)     // 5120 fp16
#define GEMM_SMEM (NSTAGE * (A_STAGE + B_STAGE) * 2)   // 56832 B

__global__ __launch_bounds__(256, 2) void gemm_mma(int HW) {
    extern __shared__ __align__(16) __half hsm[];
    __half* As = hsm;                       // [NSTAGE][BK][APAD_A]
    __half* Bs = hsm + NSTAGE * A_STAGE;    // [NSTAGE][BN][BPAD_B]

    const int tid  = threadIdx.x;
    const int wid  = tid >> 5;
    const int lane = tid & 31;
    const int g    = lane >> 2;
    const int tig  = lane & 3;
    const int wm   = (wid & 1) * 64;
    const int wn   = (wid >> 1) * 32;

    const int m0 = blockIdx.x * BM;
    const int n0 = blockIdx.y * BN;
    const int b  = m0 / HW;
    const int hw0 = m0 - b * HW;

    // global->smem mapping (two 16B cp.async per operand per thread)
    const int ark = tid >> 4;          // A: k row 0..15 (+16 for second)
    const int arm = (tid & 15) * 8;    // A: 8 fp16 (16B) along m
    const int brn = tid >> 1;          // B: n row 0..127
    const int brk = (tid & 1) * 8;     // B: 8 fp16 (16B) along k (+16 for second)

    const __half* Abase = g_Ah + ((size_t)b * C_IMG + ark) * HW + hw0 + arm;
    const __half* Bbase = g_Bh + (size_t)(n0 + brn) * C_IMG + brk;

    const uint32_t sa = (uint32_t)__cvta_generic_to_shared(As) +
                        (uint32_t)(ark * APAD_A + arm) * 2u;
    const uint32_t sb = (uint32_t)__cvta_generic_to_shared(Bs) +
                        (uint32_t)(brn * BPAD_B + brk) * 2u;

    // prologue: stages 0 and 1
    #pragma unroll
    for (int s = 0; s < 2; s++) {
        const __half* ap = Abase + (size_t)(s * BK) * HW;
        const __half* bp = Bbase + s * BK;
        const uint32_t da = sa + s * (A_STAGE * 2);
        const uint32_t db = sb + s * (B_STAGE * 2);
        cp16(da,                    ap);
        cp16(da + 16 * APAD_A * 2,  ap + (size_t)16 * HW);
        cp16(db,                    bp);
        cp16(db + 16 * 2,           bp + 16);
        asm volatile("cp.async.commit_group;" ::: "memory");
    }

    // lane-constant fragment smem offsets (bytes)
    // A (.x4.trans): k row = ((lane>>4)<<3)+(lane&7), m col = +8 if bit3
    const uint32_t a_frag_off =
        ((uint32_t)((((lane >> 4) << 3) + (lane & 7)) * APAD_A +
                    wm + ((lane >> 3) & 1) * 8)) * 2u;
    // B (.x2): n row = wn + (lane&7), k col = +8 if bit3 (lanes 0..15 used)
    const uint32_t b_frag_off =
        ((uint32_t)((wn + (lane & 7)) * BPAD_B + ((lane >> 3) & 1) * 8)) * 2u;

    const uint32_t as0 = (uint32_t)__cvta_generic_to_shared(As);
    const uint32_t bs0 = (uint32_t)__cvta_generic_to_shared(Bs);

    float acc[4][4][4];
    #pragma unroll
    for (int i = 0; i < 4; i++)
        #pragma unroll
        for (int j = 0; j < 4; j++)
            #pragma unroll
            for (int r = 0; r < 4; r++) acc[i][j][r] = 0.f;

    for (int i = 0; i < NCHUNK; i++) {
        const int buf = i % NSTAGE;

        if (i < NCHUNK - 1) {
            asm volatile("cp.async.wait_group 1;" ::: "memory");
        } else {
            asm volatile("cp.async.wait_group 0;" ::: "memory");
        }
        __syncthreads();

        if (i + 2 < NCHUNK) {
            const int s = (i + 2) % NSTAGE;
            const __half* ap = Abase + (size_t)((i + 2) * BK) * HW;
            const __half* bp = Bbase + (i + 2) * BK;
            const uint32_t da = sa + s * (A_STAGE * 2);
            const uint32_t db = sb + s * (B_STAGE * 2);
            cp16(da,                    ap);
            cp16(da + 16 * APAD_A * 2,  ap + (size_t)16 * HW);
            cp16(db,                    bp);
            cp16(db + 16 * 2,           bp + 16);
            asm volatile("cp.async.commit_group;" ::: "memory");
        }

        const uint32_t as_b = as0 + buf * (A_STAGE * 2) + a_frag_off;
        const uint32_t bs_b = bs0 + buf * (B_STAGE * 2) + b_frag_off;

        #pragma unroll
        for (int j = 0; j < 2; j++) {          // two k-steps per stage
            const uint32_t as_j = as_b + (uint32_t)(j * 16 * APAD_A * 2);
            const uint32_t bs_j = bs_b + (uint32_t)(j * 16 * 2);

            uint32_t af[4][4], bf[4][2];
            #pragma unroll
            for (int mf = 0; mf < 4; mf++)
                ldsm_x4_trans(af[mf], as_j + (uint32_t)(mf * 16 * 2));
            #pragma unroll
            for (int nf = 0; nf < 4; nf++)
                ldsm_x2(bf[nf], bs_j + (uint32_t)(nf * 8 * BPAD_B * 2));

            #pragma unroll
            for (int mf = 0; mf < 4; mf++)
                #pragma unroll
                for (int nf = 0; nf < 4; nf++)
                    mma_f16(acc[mf][nf], af[mf], bf[nf]);
        }
    }

    // Epilogue: c0,c1 -> row g, cols 2tig..2tig+1 ; c2,c3 -> row g+8
    #pragma unroll
    for (int mf = 0; mf < 4; mf++) {
        const int r0 = m0 + wm + mf * 16 + g;
        #pragma unroll
        for (int nf = 0; nf < 4; nf++) {
            const int c = n0 + wn + nf * 8 + 2 * tig;
            *reinterpret_cast<float2*>(g_G + (size_t)r0 * C_PT + c) =
                make_float2(acc[mf][nf][0], acc[mf][nf][1]);
            *reinterpret_cast<float2*>(g_G + (size_t)(r0 + 8) * C_PT + c) =
                make_float2(acc[mf][nf][2], acc[mf][nf][3]);
        }
    }
}

// ---------------------------------------------------------------------------
// Phase 2a: per-point projection -> weights + premultiplied G offsets
// ---------------------------------------------------------------------------
__global__ void proj_kernel(
    const float* __restrict__ centers,
    const float* __restrict__ P2,
    const float* __restrict__ R0,
    const float* __restrict__ Tr,
    const int*   __restrict__ bidx,
    const int*   __restrict__ hp,
    const int*   __restrict__ wp,
    int N)
{
    const int n = blockIdx.x * 256 + threadIdx.x;
    if (n >= N) return;

    const int b = bidx[n];
    const float px = centers[n * 3 + 0];
    const float py = centers[n * 3 + 1];
    const float pz = centers[n * 3 + 2];

    const float* tr = Tr + (size_t)b * 16;
    const float c0 = tr[0]  * px + tr[1]  * py + tr[2]  * pz + tr[3];
    const float c1 = tr[4]  * px + tr[5]  * py + tr[6]  * pz + tr[7];
    const float c2 = tr[8]  * px + tr[9]  * py + tr[10] * pz + tr[11];
    const float c3 = tr[12] * px + tr[13] * py + tr[14] * pz + tr[15];

    const float* r = R0 + (size_t)b * 16;
    const float e0 = r[0]  * c0 + r[1]  * c1 + r[2]  * c2 + r[3]  * c3;
    const float e1 = r[4]  * c0 + r[5]  * c1 + r[6]  * c2 + r[7]  * c3;
    const float e2 = r[8]  * c0 + r[9]  * c1 + r[10] * c2 + r[11] * c3;
    const float e3 = r[12] * c0 + r[13] * c1 + r[14] * c2 + r[15] * c3;

    const float* pm = P2 + (size_t)b * 12;
    const float iu = pm[0] * e0 + pm[1] * e1 + pm[2]  * e2 + pm[3]  * e3;
    const float iv = pm[4] * e0 + pm[5] * e1 + pm[6]  * e2 + pm[7]  * e3;
    const float iz = pm[8] * e0 + pm[9] * e1 + pm[10] * e2 + pm[11] * e3;

    const float depth = fmaxf(iz, 1e-5f);
    const float u = iu / depth;
    const float v = iv / depth;

    const int Wf = wp[0];
    const int Hf = hp[0];
    const bool valid = (iz > 0.f) && (u >= 0.f) && (u < (float)Wf) &&
                       (v >= 0.f) && (v < (float)Hf);

    const float x0f = floorf(u), y0f = floorf(v);
    const float wx1 = u - x0f, wx0 = 1.f - wx1;
    const float wy1 = v - y0f, wy0 = 1.f - wy1;
    const float vw = valid ? 1.f : 0.f;

    const float x1f = x0f + 1.f, y1f = y0f + 1.f;
    const bool bx0 = (x0f >= 0.f) && (x0f <= (float)(Wf - 1));
    const bool bx1 = (x1f >= 0.f) && (x1f <= (float)(Wf - 1));
    const bool by0 = (y0f >= 0.f) && (y0f <= (float)(Hf - 1));
    const bool by1 = (y1f >= 0.f) && (y1f <= (float)(Hf - 1));

    const float w00 = wx0 * wy0 * vw * (float)(bx0 && by0);
    const float w10 = wx1 * wy0 * vw * (float)(bx1 && by0);
    const float w01 = wx0 * wy1 * vw * (float)(bx0 && by1);
    const float w11 = wx1 * wy1 * vw * (float)(bx1 && by1);

    const int x0c = min(max((int)x0f, 0), Wf - 1);
    const int x1c = min(max((int)x0f + 1, 0), Wf - 1);
    const int y0c = min(max((int)y0f, 0), Hf - 1);
    const int y1c = min(max((int)y0f + 1, 0), Hf - 1);

    const int base_b = b * Hf * Wf;
    g_wts[n]  = make_float4(w00, w10, w01, w11);
    g_offs[n] = make_int4((base_b + y0c * Wf + x0c) * C_PT,
                          (base_b + y0c * Wf + x1c) * C_PT,
                          (base_b + y1c * Wf + x0c) * C_PT,
                          (base_b + y1c * Wf + x1c) * C_PT);
}

// ---------------------------------------------------------------------------
// Phase 2b: streaming blend: out = pf + bias + sum_i w_i * G[off_i]
// 64 threads per point (4 channels each), 4 points per block.
// Conditional corner loads (R7-proven: skips traffic for zero weights).
// ---------------------------------------------------------------------------
__global__ void blend_kernel(
    const float* __restrict__ pf,
    const float* __restrict__ ab,
    float*       __restrict__ out,
    int N)
{
    const int tid  = threadIdx.x;
    const int grp  = tid >> 6;
    const int lane = tid & 63;
    const int n = blockIdx.x * 4 + grp;
    if (n >= N) return;

    const float4 w = g_wts[n];
    const int4   o = g_offs[n];

    const int co = lane * 4;
    float4 acc = *reinterpret_cast<const float4*>(pf + (size_t)n * C_PT + co);
    const float4 bb = *reinterpret_cast<const float4*>(ab + co);
    acc.x += bb.x; acc.y += bb.y; acc.z += bb.z; acc.w += bb.w;

    if (w.x != 0.f) {
        const float4 gv = *reinterpret_cast<const float4*>(g_G + o.x + co);
        acc.x = fmaf(w.x, gv.x, acc.x); acc.y = fmaf(w.x, gv.y, acc.y);
        acc.z = fmaf(w.x, gv.z, acc.z); acc.w = fmaf(w.x, gv.w, acc.w);
    }
    if (w.y != 0.f) {
        const float4 gv = *reinterpret_cast<const float4*>(g_G + o.y + co);
        acc.x = fmaf(w.y, gv.x, acc.x); acc.y = fmaf(w.y, gv.y, acc.y);
        acc.z = fmaf(w.y, gv.z, acc.z); acc.w = fmaf(w.y, gv.w, acc.w);
    }
    if (w.z != 0.f) {
        const float4 gv = *reinterpret_cast<const float4*>(g_G + o.z + co);
        acc.x = fmaf(w.z, gv.x, acc.x); acc.y = fmaf(w.z, gv.y, acc.y);
        acc.z = fmaf(w.z, gv.z, acc.z); acc.w = fmaf(w.z, gv.w, acc.w);
    }
    if (w.w != 0.f) {
        const float4 gv = *reinterpret_cast<const float4*>(g_G + o.w + co);
        acc.x = fmaf(w.w, gv.x, acc.x); acc.y = fmaf(w.w, gv.y, acc.y);
        acc.z = fmaf(w.w, gv.z, acc.z); acc.w = fmaf(w.w, gv.w, acc.w);
    }

    *reinterpret_cast<float4*>(out + (size_t)n * C_PT + co) = acc;
}

// ---------------------------------------------------------------------------
// Launch
// Input order (metadata): point_feat, pillar_centers, img_feat, P2, R0, Tr,
//                         align_w, align_b, batch_idx, img_h, img_w
// ---------------------------------------------------------------------------
extern "C" void kernel_launch(void* const* d_in, const int* in_sizes, int n_in,
                              void* d_out, int out_size) {
    const float* point_feat = (const float*)d_in[0];
    const float* centers    = (const float*)d_in[1];
    const float* img        = (const float*)d_in[2];
    const float* P2         = (const float*)d_in[3];
    const float* R0         = (const float*)d_in[4];
    const float* Tr         = (const float*)d_in[5];
    const float* align_w    = (const float*)d_in[6];
    const float* align_b    = (const float*)d_in[7];
    const int*   bidx       = (const int*)d_in[8];
    const int*   img_h      = (const int*)d_in[9];
    const int*   img_w      = (const int*)d_in[10];
    float* out = (float*)d_out;

    const int N  = in_sizes[8];
    const int BS = in_sizes[3] / 12;
    const int total_img = in_sizes[2];
    const int HW = total_img / (BS * C_IMG);
    const int M  = BS * HW;

    cudaFuncSetAttribute(gemm_mma, cudaFuncAttributeMaxDynamicSharedMemorySize, GEMM_SMEM);

    // Phase 0: fp16 conversions (coalesced; no transposes needed)
    convert_w<<<(C_PT * C_IMG) / (256 * 4), 256>>>(align_w);
    convert_img<<<(total_img / 8 + 255) / 256, 256>>>(img, total_img);

    // Phase 2a: cheap projection (independent of GEMM)
    proj_kernel<<<(N + 255) / 256, 256>>>(centers, P2, R0, Tr, bidx, img_h, img_w, N);

    // Phase 1: G = img @ W^T via fp16 mma m16n8k16 (3-stage cp.async, BK=32)
    gemm_mma<<<dim3(M / BM, C_PT / BN), 256, GEMM_SMEM>>>(HW);

    // Phase 2b: streaming blend
    blend_kernel<<<(N + 3) / 4, 256>>>(point_feat, align_b, out, N);
}